// round 13
// baseline (speedup 1.0000x reference)
#include <cuda_runtime.h>
#include <cuda_bf16.h>
#include <math.h>
#include <stdint.h>

#define N_PTS   29696
#define NZ      32
#define KCLU    100
#define EPSF    1e-5f
#define INDEXF  29696.0f
#define NBLK_PTS 116          // N_PTS / 256
#define NBLK_RE  1856         // (1024/128) * (29696/128)
#define GAP_TAU 1.5e-2f

// ---------------- scratch (static device globals; no allocation) -------------
__device__ __nv_bfloat16 g_xb [(size_t)N_PTS * 1024];
__device__ __nv_bfloat16 g_Pb [(size_t)N_PTS * 2048];   // h3, then d1
__device__ __nv_bfloat16 g_h1b[(size_t)N_PTS * 512];    // h1, then d2
__device__ __nv_bfloat16 g_h2b[(size_t)N_PTS * 512];    // h2, then d3
__device__ __nv_bfloat16 g_zbh[(size_t)N_PTS * NZ];     // z in bf16 (decoder input)
__device__ float g_z [(size_t)N_PTS * NZ];              // z in fp32 (cluster input)
__device__ float g_q [(size_t)N_PTS * KCLU];
__device__ __nv_bfloat16 g_wbt[3712 * 1024];            // transposed bf16 weights
__device__ float g_upart[NBLK_PTS * KCLU];
__device__ float g_Spart[NBLK_PTS];
__device__ float g_klpart[NBLK_PTS];
__device__ float g_repart[NBLK_RE];
__device__ int   g_cnt[KCLU];
__device__ float g_f[KCLU];
__device__ int   g_nflag;
__device__ int   g_flaglist[N_PTS];

// offsets (elements) into g_wbt
#define OFF_WE1 0            // [512][1024]
#define OFF_WE2 (512*1024)   // [512][512]
#define OFF_WE3 (768*1024)   // [2048][512]
#define OFF_WZ  (1792*1024)  // [32][2048]
#define OFF_WD1 (1856*1024)  // [2048][32]
#define OFF_WD2 (1920*1024)  // [512][2048]
#define OFF_WD3 (2944*1024)  // [512][512]
#define OFF_WXB (3200*1024)  // [1024][512]

// ---------------- helpers ------------------------------------------------------
__device__ __forceinline__ uint32_t smem_u32(const void* p) {
    uint32_t a;
    asm("{ .reg .u64 t; cvta.to.shared.u64 t, %1; cvt.u32.u64 %0, t; }" : "=r"(a) : "l"(p));
    return a;
}
__device__ __forceinline__ void cp_async16(uint32_t s, const void* g) {
    asm volatile("cp.async.cg.shared.global [%0], [%1], 16;" :: "r"(s), "l"(g));
}
#define CP_COMMIT() asm volatile("cp.async.commit_group;" ::: "memory")
#define CP_WAIT1()  asm volatile("cp.async.wait_group 1;" ::: "memory")
#define CP_WAIT0()  asm volatile("cp.async.wait_group 0;" ::: "memory")
#define MMA_BF16(c, a, b) \
    asm volatile("mma.sync.aligned.m16n8k16.row.col.f32.bf16.bf16.f32 " \
        "{%0,%1,%2,%3}, {%4,%5,%6,%7}, {%8,%9}, {%0,%1,%2,%3};" \
        : "+f"((c)[0]), "+f"((c)[1]), "+f"((c)[2]), "+f"((c)[3]) \
        : "r"((a)[0]), "r"((a)[1]), "r"((a)[2]), "r"((a)[3]), \
          "r"((b)[0]), "r"((b)[1]))

__global__ void init_kernel() {
    int tid = threadIdx.x;
    if (tid < KCLU) g_cnt[tid] = 0;
    if (tid == 0) g_nflag = 0;
}
__global__ void fill_zero_kernel(float* p, int n) {
    int i = blockIdx.x * blockDim.x + threadIdx.x;
    if (i < n) p[i] = 0.0f;
}
// fp32 -> bf16 flat convert (n2 = count/2)
__global__ void conv_bf16_kernel(const float2* __restrict__ in,
                                 __nv_bfloat162* __restrict__ out, int n2) {
    int i = blockIdx.x * blockDim.x + threadIdx.x;
    if (i < n2) {
        float2 v = in[i];
        out[i] = __floats2bfloat162_rn(v.x, v.y);
    }
}
// transpose + convert: W fp32 [K,N] -> Wt bf16 [N,K]; grid(N/32, K/32), block(32,8)
__global__ void tconv_kernel(const float* __restrict__ in, __nv_bfloat16* __restrict__ out,
                             int Kd, int Nd) {
    __shared__ float t[32][33];
    int n0 = blockIdx.x * 32, k0 = blockIdx.y * 32;
    int tx = threadIdx.x, ty = threadIdx.y;
    for (int i = ty; i < 32; i += 8) t[i][tx] = in[(size_t)(k0 + i) * Nd + n0 + tx];
    __syncthreads();
    for (int i = ty; i < 32; i += 8)
        out[(size_t)(n0 + i) * Kd + k0 + tx] = __float2bfloat16_rn(t[tx][i]);
}

// ---------------- bf16 mma.sync GEMM (cp.async, padded tiles) ------------------
// acc = A[M,K](bf16) @ Wt[N,K](bf16)^T, fp32 accum; + bias, then:
// EPI 0: relu -> bf16 store to Cb.  EPI 1: raw fp32 -> Cf AND bf16 -> Cb.
// EPI 2: fused sum((v-X)^2) block partials.
// Block 256 thr = 8 warps (2m x 4n); block tile 128 x BN; warp tile 64 x BN/4.
template <int BN, int EPI>
__global__ void __launch_bounds__(256, 2)
mma_gemm(const __nv_bfloat16* __restrict__ A, const __nv_bfloat16* __restrict__ Bt,
         const float* __restrict__ bias, __nv_bfloat16* __restrict__ Cb,
         float* __restrict__ Cf, const float* __restrict__ X,
         float* __restrict__ part, int N, int K) {
    extern __shared__ char smem[];
    __nv_bfloat16* smh = reinterpret_cast<__nv_bfloat16*>(smem);
    constexpr int LDT = 40;                   // halves; padded -> conflict-free frags
    constexpr int A_TILE_H = 128 * LDT;
    constexpr int B_TILE_H = BN * LDT;
    constexpr int STAGE_H = A_TILE_H + B_TILE_H;
    constexpr int NTL = BN / 32;
    constexpr int WN = BN / 4;
    constexpr int BCH = BN * 4;               // B 16B-chunks per tile

    const int tid = threadIdx.x;
    const int wid = tid >> 5;
    const int lane = tid & 31;
    const int g = lane >> 2;
    const int t = lane & 3;
    const int warp_m = wid >> 2;
    const int warp_n = wid & 3;
    const int bm = blockIdx.y * 128, bn = blockIdx.x * BN;
    const uint32_t sb = smem_u32(smh);

    float acc[4][NTL][4];
#pragma unroll
    for (int mt = 0; mt < 4; mt++)
#pragma unroll
        for (int nt = 0; nt < NTL; nt++)
#pragma unroll
            for (int i = 0; i < 4; i++) acc[mt][nt][i] = 0.0f;

    const int NC = K >> 5;

    auto prefetch = [&](int c, int s) {
        const int k0 = c << 5;
        const uint32_t base = sb + (uint32_t)s * STAGE_H * 2;
#pragma unroll
        for (int i = 0; i < 2; i++) {                      // A: 512 chunks
            int idx = tid + i * 256;
            int r = idx >> 2, ch = idx & 3;
            cp_async16(base + (r * LDT + ch * 8) * 2,
                       &A[(size_t)(bm + r) * K + k0 + ch * 8]);
        }
#pragma unroll
        for (int i = 0; i < (BCH + 255) / 256; i++) {      // B: BN*4 chunks
            int idx = tid + i * 256;
            if (BCH >= 256 || idx < BCH) {
                int r = idx >> 2, ch = idx & 3;
                cp_async16(base + (A_TILE_H + r * LDT + ch * 8) * 2,
                           &Bt[(size_t)(bn + r) * K + k0 + ch * 8]);
            }
        }
    };

    auto compute = [&](int s) {
        const __nv_bfloat16* As = smh + s * STAGE_H;
        const __nv_bfloat16* Bs = As + A_TILE_H;
#pragma unroll
        for (int s16 = 0; s16 < 2; s16++) {
            const int kb = s16 * 16 + 2 * t;
            uint32_t bf[NTL][2];
#pragma unroll
            for (int nt = 0; nt < NTL; nt++) {
                int nb = warp_n * WN + nt * 8 + g;
                bf[nt][0] = *reinterpret_cast<const uint32_t*>(&Bs[nb * LDT + kb]);
                bf[nt][1] = *reinterpret_cast<const uint32_t*>(&Bs[nb * LDT + kb + 8]);
            }
#pragma unroll
            for (int mt = 0; mt < 4; mt++) {
                int mb = warp_m * 64 + mt * 16 + g;
                uint32_t af[4];
                af[0] = *reinterpret_cast<const uint32_t*>(&As[mb * LDT + kb]);
                af[1] = *reinterpret_cast<const uint32_t*>(&As[(mb + 8) * LDT + kb]);
                af[2] = *reinterpret_cast<const uint32_t*>(&As[mb * LDT + kb + 8]);
                af[3] = *reinterpret_cast<const uint32_t*>(&As[(mb + 8) * LDT + kb + 8]);
#pragma unroll
                for (int nt = 0; nt < NTL; nt++) MMA_BF16(acc[mt][nt], af, bf[nt]);
            }
        }
    };

    // ---- pipelined mainloop (2-stage cp.async) ----
    prefetch(0, 0);
    CP_COMMIT();
    if (NC > 1) { prefetch(1, 1); CP_COMMIT(); CP_WAIT1(); }
    else        { CP_WAIT0(); }
    __syncthreads();
#pragma unroll 1
    for (int c = 0; c < NC; c++) {
        compute(c & 1);
        __syncthreads();
        if (c + 2 < NC) {
            prefetch(c + 2, c & 1);
            CP_COMMIT();
            CP_WAIT1();
        } else if (c + 1 < NC) {
            CP_WAIT0();
        }
        __syncthreads();
    }

    // ---- epilogue straight from accumulators ----
    float lsum = 0.0f;
#pragma unroll
    for (int mt = 0; mt < 4; mt++) {
#pragma unroll
        for (int nt = 0; nt < NTL; nt++) {
            int row = bm + warp_m * 64 + mt * 16 + g;
            int col = bn + warp_n * WN + nt * 8 + 2 * t;
            float b0 = bias[col], b1 = bias[col + 1];
            float v0 = acc[mt][nt][0] + b0, v1 = acc[mt][nt][1] + b1;
            float v2 = acc[mt][nt][2] + b0, v3 = acc[mt][nt][3] + b1;
            size_t i0 = (size_t)row * N + col;
            size_t i1 = (size_t)(row + 8) * N + col;
            if (EPI == 0) {
                v0 = fmaxf(v0, 0.0f); v1 = fmaxf(v1, 0.0f);
                v2 = fmaxf(v2, 0.0f); v3 = fmaxf(v3, 0.0f);
                *reinterpret_cast<__nv_bfloat162*>(&Cb[i0]) = __floats2bfloat162_rn(v0, v1);
                *reinterpret_cast<__nv_bfloat162*>(&Cb[i1]) = __floats2bfloat162_rn(v2, v3);
            } else if (EPI == 1) {
                *reinterpret_cast<float2*>(&Cf[i0]) = make_float2(v0, v1);
                *reinterpret_cast<float2*>(&Cf[i1]) = make_float2(v2, v3);
                *reinterpret_cast<__nv_bfloat162*>(&Cb[i0]) = __floats2bfloat162_rn(v0, v1);
                *reinterpret_cast<__nv_bfloat162*>(&Cb[i1]) = __floats2bfloat162_rn(v2, v3);
            } else {
                float2 x0 = *reinterpret_cast<const float2*>(&X[i0]);
                float2 x1 = *reinterpret_cast<const float2*>(&X[i1]);
                float d0 = v0 - x0.x, d1 = v1 - x0.y, d2 = v2 - x1.x, d3 = v3 - x1.y;
                lsum += d0 * d0 + d1 * d1 + d2 * d2 + d3 * d3;
            }
        }
    }
    if (EPI == 2) {
        __syncthreads();
        float* red = reinterpret_cast<float*>(smem);
        red[tid] = lsum;
        __syncthreads();
        for (int s2 = 128; s2 > 0; s2 >>= 1) {
            if (tid < s2) red[tid] += red[tid + s2];
            __syncthreads();
        }
        if (tid == 0) part[blockIdx.y * gridDim.x + blockIdx.x] = red[0];
    }
}

// ---------------- clustering pass A -------------------------------------------
__global__ void cluster_pass(const float* __restrict__ t1,
                             const float* __restrict__ clu,
                             float* __restrict__ out_predict) {
    __shared__ float cs[KCLU * NZ];
    __shared__ float u_s[KCLU];
    __shared__ float red[256];
    int tid = threadIdx.x;
    for (int i = tid; i < KCLU * NZ; i += 256) cs[i] = clu[i];
    if (tid < KCLU) u_s[tid] = 0.0f;
    __syncthreads();

    int p = blockIdx.x * 256 + tid;
    float zr[NZ];
    const float* zp = g_z + (size_t)p * NZ;
#pragma unroll
    for (int i = 0; i < NZ; i++) zr[i] = zp[i];

    float cm = (t1[p * 3 + 0] * 0.01f) * (t1[p * 3 + 1] * 0.01f) * (t1[p * 3 + 2] * 0.01f)
               * 0.99f + 1.0f;
    float s = 0.0f;
#pragma unroll
    for (int i = 0; i < NZ; i++) { zr[i] *= cm; s += zr[i]; }
    float mean = s * (1.0f / NZ);
    float var = 0.0f;
#pragma unroll
    for (int i = 0; i < NZ; i++) { float d = zr[i] - mean; var += d * d; }
    float isd = 1.0f / sqrtf(var * (1.0f / (NZ - 1)));
#pragma unroll
    for (int i = 0; i < NZ; i++) zr[i] = (zr[i] - mean) * isd;

    float sumq = 0.0f, best = -1.0f, best2 = -1.0f;
    int bi = 0;
    for (int j = 0; j < KCLU; j++) {
        const float* c = &cs[j * NZ];
        float d = 0.0f;
#pragma unroll
        for (int i = 0; i < NZ; i++) { float tt = zr[i] - c[i]; d += tt * tt; }
        float qu = EPSF + d;
        sumq += qu;
        if (qu > best) { best2 = best; best = qu; bi = j; }
        else if (qu > best2) best2 = qu;
    }
    out_predict[p] = (float)bi;
    atomicAdd(&g_cnt[bi], 1);
    if (best - best2 < GAP_TAU * best) {       // near-tie: flag for fp32 rescue
        int ii = atomicAdd(&g_nflag, 1);
        g_flaglist[ii] = p;
    }

    float inv = 1.0f / sumq;
    float Sl = 0.0f;
    float* qrow = g_q + (size_t)p * KCLU;
    for (int j = 0; j < KCLU; j++) {
        const float* c = &cs[j * NZ];
        float d = 0.0f;
#pragma unroll
        for (int i = 0; i < NZ; i++) { float tt = zr[i] - c[i]; d += tt * tt; }
        float qn = (EPSF + d) * inv;
        qrow[j] = qn;
        atomicAdd(&u_s[j], qn);
        float lq = logf(qn);
        float tq = (1.0f - qn) * (1.0f - qn) * lq * INDEXF;
        Sl += sqrtf(-1.0f / tq);
    }

    red[tid] = Sl;
    __syncthreads();
    for (int s2 = 128; s2 > 0; s2 >>= 1) {
        if (tid < s2) red[tid] += red[tid + s2];
        __syncthreads();
    }
    if (tid == 0) g_Spart[blockIdx.x] = red[0];
    __syncthreads();
    if (tid < KCLU) g_upart[blockIdx.x * KCLU + tid] = u_s[tid];
}

// ---------------- fp32 rescue for near-tie points ------------------------------
#define RB 8
__global__ void __launch_bounds__(256, 1)
rescue_kernel(const float* __restrict__ x, const float* __restrict__ t1,
              const float* __restrict__ clu,
              const float* __restrict__ We1, const float* __restrict__ be1,
              const float* __restrict__ We2, const float* __restrict__ be2,
              const float* __restrict__ We3, const float* __restrict__ be3,
              const float* __restrict__ Wz,  const float* __restrict__ bz,
              float* __restrict__ out_predict) {
    extern __shared__ float sm[];
    float* xb  = sm;                  // [1024][RB]
    float* hh  = xb + RB * 1024;      // [2048][RB]
    float* s1b = hh + RB * 2048;      // [512][RB]
    float* s2b = s1b + RB * 512;      // [512][RB]
    float* zz  = s2b + RB * 512;      // [RB][32]
    float* pz  = zz + RB * 32;        // [8][32][RB]
    float* dst = pz + 8 * 32 * RB;    // [128]
    const int tid = threadIdx.x;
    const int nf = g_nflag;

    for (int base = blockIdx.x * RB; base < nf; base += gridDim.x * RB) {
        const int cb = min(RB, nf - base);
        int plist[RB];
#pragma unroll
        for (int i = 0; i < RB; i++) plist[i] = g_flaglist[base + (i < cb ? i : 0)];
        __syncthreads();
        for (int k = tid; k < 1024; k += 256) {
#pragma unroll
            for (int i = 0; i < RB; i++)
                xb[k * RB + i] = x[(size_t)plist[i] * 1024 + k];
        }
        __syncthreads();
        for (int n = tid; n < 512; n += 256) {
            float acc[RB] = {};
            for (int k = 0; k < 1024; k++) {
                float w = We1[(size_t)k * 512 + n];
                float4 v0 = *reinterpret_cast<const float4*>(&xb[k * RB]);
                float4 v1 = *reinterpret_cast<const float4*>(&xb[k * RB + 4]);
                acc[0] += v0.x * w; acc[1] += v0.y * w; acc[2] += v0.z * w; acc[3] += v0.w * w;
                acc[4] += v1.x * w; acc[5] += v1.y * w; acc[6] += v1.z * w; acc[7] += v1.w * w;
            }
            float b = be1[n];
#pragma unroll
            for (int i = 0; i < RB; i++) s1b[n * RB + i] = fmaxf(acc[i] + b, 0.0f);
        }
        __syncthreads();
        for (int n = tid; n < 512; n += 256) {
            float acc[RB] = {};
            for (int k = 0; k < 512; k++) {
                float w = We2[(size_t)k * 512 + n];
                float4 v0 = *reinterpret_cast<const float4*>(&s1b[k * RB]);
                float4 v1 = *reinterpret_cast<const float4*>(&s1b[k * RB + 4]);
                acc[0] += v0.x * w; acc[1] += v0.y * w; acc[2] += v0.z * w; acc[3] += v0.w * w;
                acc[4] += v1.x * w; acc[5] += v1.y * w; acc[6] += v1.z * w; acc[7] += v1.w * w;
            }
            float b = be2[n];
#pragma unroll
            for (int i = 0; i < RB; i++) s2b[n * RB + i] = fmaxf(acc[i] + b, 0.0f);
        }
        __syncthreads();
        for (int n = tid; n < 2048; n += 256) {
            float acc[RB] = {};
            for (int k = 0; k < 512; k++) {
                float w = We3[(size_t)k * 2048 + n];
                float4 v0 = *reinterpret_cast<const float4*>(&s2b[k * RB]);
                float4 v1 = *reinterpret_cast<const float4*>(&s2b[k * RB + 4]);
                acc[0] += v0.x * w; acc[1] += v0.y * w; acc[2] += v0.z * w; acc[3] += v0.w * w;
                acc[4] += v1.x * w; acc[5] += v1.y * w; acc[6] += v1.z * w; acc[7] += v1.w * w;
            }
            float b = be3[n];
#pragma unroll
            for (int i = 0; i < RB; i++) hh[n * RB + i] = fmaxf(acc[i] + b, 0.0f);
        }
        __syncthreads();
        {
            int n = tid & 31, kc = tid >> 5;
            float acc[RB] = {};
            for (int k = kc * 256; k < kc * 256 + 256; k++) {
                float w = Wz[(size_t)k * 32 + n];
                float4 v0 = *reinterpret_cast<const float4*>(&hh[k * RB]);
                float4 v1 = *reinterpret_cast<const float4*>(&hh[k * RB + 4]);
                acc[0] += v0.x * w; acc[1] += v0.y * w; acc[2] += v0.z * w; acc[3] += v0.w * w;
                acc[4] += v1.x * w; acc[5] += v1.y * w; acc[6] += v1.z * w; acc[7] += v1.w * w;
            }
#pragma unroll
            for (int i = 0; i < RB; i++) pz[(kc * 32 + n) * RB + i] = acc[i];
        }
        __syncthreads();
        if (tid < 32) {
            int n = tid;
            float b = bz[n];
#pragma unroll
            for (int i = 0; i < RB; i++) {
                float s = 0.0f;
                for (int kc = 0; kc < 8; kc++) s += pz[(kc * 32 + n) * RB + i];
                zz[i * 32 + n] = s + b;
            }
        }
        __syncthreads();
        if (tid < cb) {
            int i = tid;
            int p = plist[i];
            float cm = (t1[p * 3 + 0] * 0.01f) * (t1[p * 3 + 1] * 0.01f) *
                       (t1[p * 3 + 2] * 0.01f) * 0.99f + 1.0f;
            float s = 0.0f;
            for (int k = 0; k < NZ; k++) { zz[i * 32 + k] *= cm; s += zz[i * 32 + k]; }
            float mean = s * (1.0f / NZ);
            float var = 0.0f;
            for (int k = 0; k < NZ; k++) { float d = zz[i * 32 + k] - mean; var += d * d; }
            float isd = 1.0f / sqrtf(var * (1.0f / (NZ - 1)));
            for (int k = 0; k < NZ; k++) zz[i * 32 + k] = (zz[i * 32 + k] - mean) * isd;
        }
        __syncthreads();
        for (int i = 0; i < cb; i++) {
            if (tid < KCLU) {
                float d = 0.0f;
                for (int k = 0; k < NZ; k++) {
                    float tt = zz[i * 32 + k] - clu[tid * NZ + k];
                    d += tt * tt;
                }
                dst[tid] = d;
            }
            __syncthreads();
            if (tid == 0) {
                float best = -1.0f; int bi = 0;
                for (int j = 0; j < KCLU; j++)
                    if (dst[j] > best) { best = dst[j]; bi = j; }
                int p = plist[i];
                int old = (int)out_predict[p];
                if (old != bi) {
                    atomicAdd(&g_cnt[old], -1);
                    atomicAdd(&g_cnt[bi], 1);
                    out_predict[p] = (float)bi;
                }
            }
            __syncthreads();
        }
    }
}

// ---------------- stats pass B -------------------------------------------------
__global__ void stats_kernel() {
    __shared__ float u[KCLU];
    __shared__ float sred[128];
    int tid = threadIdx.x;
    if (tid < KCLU) {
        float s = 0.0f;
        for (int b = 0; b < NBLK_PTS; b++) s += g_upart[b * KCLU + tid];
        u[tid] = s;
    }
    float sp = (tid < NBLK_PTS) ? g_Spart[tid] : 0.0f;
    sred[tid] = sp;
    __syncthreads();
    for (int s = 64; s > 0; s >>= 1) {
        if (tid < s) sred[tid] += sred[tid + s];
        __syncthreads();
    }
    if (tid == 0) {
        float S = sred[0];
        float um = 0.0f;
        for (int j = 0; j < KCLU; j++) um += u[j];
        um /= KCLU;
        float uv = 0.0f;
        for (int j = 0; j < KCLU; j++) { float d = u[j] - um; uv += d * d; }
        float usd = sqrtf(uv / (KCLU - 1));

        float v[KCLU];
        float vm = 0.0f;
        for (int j = 0; j < KCLU; j++) {
            int c = g_cnt[j]; if (c < 1) c = 1;
            v[j] = sqrtf((float)c) * S;
            vm += v[j];
        }
        vm /= KCLU;
        float vv = 0.0f;
        for (int j = 0; j < KCLU; j++) { float d = v[j] - vm; vv += d * d; }
        float vsd = sqrtf(vv / (KCLU - 1));

        float umin = 1e30f, vmin = 1e30f;
        for (int j = 0; j < KCLU; j++) {
            float un = (u[j] - um) / usd;
            float vn = (v[j] - vm) / vsd;
            u[j] = un; v[j] = vn;
            if (un < umin) umin = un;
            if (vn < vmin) vmin = vn;
        }
        for (int j = 0; j < KCLU; j++)
            g_f[j] = (u[j] - umin + 0.001f) + (v[j] - vmin + 0.001f) + 1.0f;
    }
}

// ---------------- KL pass C -----------------------------------------------------
__global__ void kl_pass() {
    __shared__ float fs[KCLU];
    __shared__ float red[256];
    int tid = threadIdx.x;
    if (tid < KCLU) fs[tid] = g_f[tid];
    __syncthreads();
    int p = blockIdx.x * 256 + tid;
    const float* qrow = g_q + (size_t)p * KCLU;
    float sw = 0.0f;
    for (int j = 0; j < KCLU; j++) { float q = qrow[j]; sw += q * q / fs[j]; }
    float inv = 1.0f / sw;
    float kl = 0.0f;
    for (int j = 0; j < KCLU; j++) {
        float q = qrow[j];
        float pj = q * q / fs[j] * inv;
        kl += pj * (logf(pj) - logf(q));
    }
    red[tid] = kl;
    __syncthreads();
    for (int s2 = 128; s2 > 0; s2 >>= 1) {
        if (tid < s2) red[tid] += red[tid + s2];
        __syncthreads();
    }
    if (tid == 0) g_klpart[blockIdx.x] = red[0];
}

// ---------------- final loss ----------------------------------------------------
__global__ void final_kernel(const float* __restrict__ clu, float* __restrict__ out) {
    __shared__ float red[256];
    int tid = threadIdx.x;
    float kl = 0.0f;
    for (int i = tid; i < NBLK_PTS; i += 256) kl += g_klpart[i];
    float re = 0.0f;
    for (int i = tid; i < NBLK_RE; i += 256) re += g_repart[i];
    float D = 0.0f;
    for (int idx = tid; idx < KCLU * KCLU; idx += 256) {
        int i = idx / KCLU, j = idx % KCLU;
        float d = 0.0f;
        for (int kk = 0; kk < NZ; kk++) {
            float t = clu[i * NZ + kk] - clu[j * NZ + kk];
            d += t * t;
        }
        D += d;
    }
    red[tid] = kl; __syncthreads();
    for (int s = 128; s > 0; s >>= 1) { if (tid < s) red[tid] += red[tid + s]; __syncthreads(); }
    float kls = red[0]; __syncthreads();
    red[tid] = re; __syncthreads();
    for (int s = 128; s > 0; s >>= 1) { if (tid < s) red[tid] += red[tid + s]; __syncthreads(); }
    float res = red[0]; __syncthreads();
    red[tid] = D; __syncthreads();
    for (int s = 128; s > 0; s >>= 1) { if (tid < s) red[tid] += red[tid + s]; __syncthreads(); }
    if (tid == 0) {
        float kl_loss = 0.01f * kls / ((float)N_PTS * (float)KCLU);
        float re_loss = res / ((float)N_PTS * 1024.0f);
        float mean_d = red[0] / (float)(KCLU * KCLU - KCLU);
        out[N_PTS] = kl_loss + re_loss + 0.01f / mean_d;
    }
}

// ---------------- host ----------------------------------------------------------
extern "C" void kernel_launch(void* const* d_in, const int* in_sizes, int n_in,
                              void* d_out, int out_size) {
    const float* x   = (const float*)d_in[0];
    const float* t1  = (const float*)d_in[1];
    const float* clu = (const float*)d_in[2];
    const float* We1 = (const float*)d_in[3];  const float* be1 = (const float*)d_in[4];
    const float* We2 = (const float*)d_in[5];  const float* be2 = (const float*)d_in[6];
    const float* We3 = (const float*)d_in[7];  const float* be3 = (const float*)d_in[8];
    const float* Wz  = (const float*)d_in[9];  const float* bz  = (const float*)d_in[10];
    const float* Wd1 = (const float*)d_in[11]; const float* bd1 = (const float*)d_in[12];
    const float* Wd2 = (const float*)d_in[13]; const float* bd2 = (const float*)d_in[14];
    const float* Wd3 = (const float*)d_in[15]; const float* bd3 = (const float*)d_in[16];
    const float* Wxb = (const float*)d_in[17]; const float* bxb = (const float*)d_in[18];
    float* out = (float*)d_out;

    __nv_bfloat16 *xb, *Pb, *h1b, *h2b, *zbh, *wbt;
    float *zf, *repart;
    cudaGetSymbolAddress((void**)&xb,  g_xb);
    cudaGetSymbolAddress((void**)&Pb,  g_Pb);
    cudaGetSymbolAddress((void**)&h1b, g_h1b);
    cudaGetSymbolAddress((void**)&h2b, g_h2b);
    cudaGetSymbolAddress((void**)&zbh, g_zbh);
    cudaGetSymbolAddress((void**)&wbt, g_wbt);
    cudaGetSymbolAddress((void**)&zf,  g_z);
    cudaGetSymbolAddress((void**)&repart, g_repart);

    constexpr int SM_128 = (128 * 40 + 128 * 40) * 2 * 2;   // 40960 B
    constexpr int SM_32  = (128 * 40 + 32 * 40) * 2 * 2;    // 25600 B
    constexpr int SM_RES = (RB * 1024 + RB * 2048 + RB * 512 + RB * 512 + RB * 32
                            + 8 * 32 * RB + 128) * 4;
    cudaFuncSetAttribute(mma_gemm<128, 0>, cudaFuncAttributeMaxDynamicSharedMemorySize, SM_128);
    cudaFuncSetAttribute(mma_gemm<32, 1>,  cudaFuncAttributeMaxDynamicSharedMemorySize, SM_32);
    cudaFuncSetAttribute(mma_gemm<128, 2>, cudaFuncAttributeMaxDynamicSharedMemorySize, SM_128);
    cudaFuncSetAttribute(rescue_kernel, cudaFuncAttributeMaxDynamicSharedMemorySize, SM_RES);

    init_kernel<<<1, 128>>>();

    // prep: x -> bf16; weights -> transposed bf16 [N,K]
    {
        int n2 = N_PTS * 1024 / 2;
        conv_bf16_kernel<<<(n2 + 255) / 256, 256>>>((const float2*)x, (__nv_bfloat162*)xb, n2);
    }
    dim3 tb(32, 8);
    tconv_kernel<<<dim3(512 / 32, 1024 / 32), tb>>>(We1, wbt + OFF_WE1, 1024, 512);
    tconv_kernel<<<dim3(512 / 32, 512 / 32), tb>>>(We2, wbt + OFF_WE2, 512, 512);
    tconv_kernel<<<dim3(2048 / 32, 512 / 32), tb>>>(We3, wbt + OFF_WE3, 512, 2048);
    tconv_kernel<<<dim3(1, 2048 / 32), tb>>>(Wz, wbt + OFF_WZ, 2048, 32);
    tconv_kernel<<<dim3(2048 / 32, 1), tb>>>(Wd1, wbt + OFF_WD1, 32, 2048);
    tconv_kernel<<<dim3(512 / 32, 2048 / 32), tb>>>(Wd2, wbt + OFF_WD2, 2048, 512);
    tconv_kernel<<<dim3(512 / 32, 512 / 32), tb>>>(Wd3, wbt + OFF_WD3, 512, 512);
    tconv_kernel<<<dim3(1024 / 32, 512 / 32), tb>>>(Wxb, wbt + OFF_WXB, 512, 1024);

    const dim3 blk(256);
    const int MB = N_PTS / 128;  // 232

    // encoder
    mma_gemm<128, 0><<<dim3(4, MB), blk, SM_128>>>(xb, wbt + OFF_WE1, be1, h1b, nullptr, nullptr, nullptr, 512, 1024);
    mma_gemm<128, 0><<<dim3(4, MB), blk, SM_128>>>(h1b, wbt + OFF_WE2, be2, h2b, nullptr, nullptr, nullptr, 512, 512);
    mma_gemm<128, 0><<<dim3(16, MB), blk, SM_128>>>(h2b, wbt + OFF_WE3, be3, Pb, nullptr, nullptr, nullptr, 2048, 512);
    mma_gemm<32, 1><<<dim3(1, MB), blk, SM_32>>>(Pb, wbt + OFF_WZ, bz, zbh, zf, nullptr, nullptr, 32, 2048);
    // decoder
    mma_gemm<128, 0><<<dim3(16, MB), blk, SM_128>>>(zbh, wbt + OFF_WD1, bd1, Pb, nullptr, nullptr, nullptr, 2048, 32);
    mma_gemm<128, 0><<<dim3(4, MB), blk, SM_128>>>(Pb, wbt + OFF_WD2, bd2, h1b, nullptr, nullptr, nullptr, 512, 2048);
    mma_gemm<128, 0><<<dim3(4, MB), blk, SM_128>>>(h1b, wbt + OFF_WD3, bd3, h2b, nullptr, nullptr, nullptr, 512, 512);
    mma_gemm<128, 2><<<dim3(8, MB), blk, SM_128>>>(h2b, wbt + OFF_WXB, bxb, nullptr, nullptr, x, repart, 1024, 512);

    // clustering + rescue + loss
    cluster_pass<<<NBLK_PTS, 256>>>(t1, clu, out);
    rescue_kernel<<<148, 256, SM_RES>>>(x, t1, clu, We1, be1, We2, be2, We3, be3, Wz, bz, out);
    stats_kernel<<<1, 128>>>();
    kl_pass<<<NBLK_PTS, 256>>>();
    final_kernel<<<1, 256>>>(clu, out);

    int extra = out_size - (N_PTS + 1);
    if (extra > 0) fill_zero_kernel<<<(extra + 255) / 256, 256>>>(out + N_PTS + 1, extra);
}

// round 14
// speedup vs baseline: 1.0419x; 1.0419x over previous
#include <cuda_runtime.h>
#include <cuda_bf16.h>
#include <math.h>
#include <stdint.h>

#define N_PTS   29696
#define NZ      32
#define KCLU    100
#define EPSF    1e-5f
#define INDEXF  29696.0f
#define NBLK_PTS 116          // N_PTS / 256
#define NBLK_RE  1856         // (1024/128) * (29696/128)
#define GAP_TAU 1.5e-2f

// ---------------- scratch (static device globals; no allocation) -------------
__device__ __nv_bfloat16 g_xb [(size_t)N_PTS * 1024];
__device__ __nv_bfloat16 g_Pb [(size_t)N_PTS * 2048];   // h3, then d1
__device__ __nv_bfloat16 g_h1b[(size_t)N_PTS * 512];    // h1, then d2
__device__ __nv_bfloat16 g_h2b[(size_t)N_PTS * 512];    // h2, then d3
__device__ __nv_bfloat16 g_zbh[(size_t)N_PTS * NZ];     // z in bf16 (decoder input)
__device__ float g_z [(size_t)N_PTS * NZ];              // z in fp32 (cluster input)
__device__ float g_q [(size_t)N_PTS * KCLU];
__device__ __nv_bfloat16 g_wbt[3712 * 1024];            // transposed bf16 weights
__device__ float g_upart[NBLK_PTS * KCLU];
__device__ float g_Spart[NBLK_PTS];
__device__ float g_klpart[NBLK_PTS];
__device__ float g_repart[NBLK_RE];
__device__ int   g_cnt[KCLU];
__device__ float g_f[KCLU];
__device__ int   g_nflag;
__device__ int   g_flaglist[N_PTS];

// offsets (elements) into g_wbt
#define OFF_WE1 0            // [512][1024]
#define OFF_WE2 (512*1024)   // [512][512]
#define OFF_WE3 (768*1024)   // [2048][512]
#define OFF_WZ  (1792*1024)  // [32][2048]
#define OFF_WD1 (1856*1024)  // [2048][32]
#define OFF_WD2 (1920*1024)  // [512][2048]
#define OFF_WD3 (2944*1024)  // [512][512]
#define OFF_WXB (3200*1024)  // [1024][512]

// ---------------- helpers ------------------------------------------------------
__device__ __forceinline__ uint32_t smem_u32(const void* p) {
    uint32_t a;
    asm("{ .reg .u64 t; cvta.to.shared.u64 t, %1; cvt.u32.u64 %0, t; }" : "=r"(a) : "l"(p));
    return a;
}
__device__ __forceinline__ void cp_async16(uint32_t s, const void* g) {
    asm volatile("cp.async.cg.shared.global [%0], [%1], 16;" :: "r"(s), "l"(g));
}
#define CP_COMMIT() asm volatile("cp.async.commit_group;" ::: "memory")
#define CP_WAIT1()  asm volatile("cp.async.wait_group 1;" ::: "memory")
#define CP_WAIT0()  asm volatile("cp.async.wait_group 0;" ::: "memory")
#define MMA_BF16(c, a, b) \
    asm volatile("mma.sync.aligned.m16n8k16.row.col.f32.bf16.bf16.f32 " \
        "{%0,%1,%2,%3}, {%4,%5,%6,%7}, {%8,%9}, {%0,%1,%2,%3};" \
        : "+f"((c)[0]), "+f"((c)[1]), "+f"((c)[2]), "+f"((c)[3]) \
        : "r"((a)[0]), "r"((a)[1]), "r"((a)[2]), "r"((a)[3]), \
          "r"((b)[0]), "r"((b)[1]))

__global__ void init_kernel() {
    int tid = threadIdx.x;
    if (tid < KCLU) g_cnt[tid] = 0;
    if (tid == 0) g_nflag = 0;
}
__global__ void fill_zero_kernel(float* p, int n) {
    int i = blockIdx.x * blockDim.x + threadIdx.x;
    if (i < n) p[i] = 0.0f;
}
__global__ void conv_bf16_kernel(const float2* __restrict__ in,
                                 __nv_bfloat162* __restrict__ out, int n2) {
    int i = blockIdx.x * blockDim.x + threadIdx.x;
    if (i < n2) {
        float2 v = in[i];
        out[i] = __floats2bfloat162_rn(v.x, v.y);
    }
}
// transpose + convert: W fp32 [K,N] -> Wt bf16 [N,K]; grid(N/32, K/32), block(32,8)
__global__ void tconv_kernel(const float* __restrict__ in, __nv_bfloat16* __restrict__ out,
                             int Kd, int Nd) {
    __shared__ float t[32][33];
    int n0 = blockIdx.x * 32, k0 = blockIdx.y * 32;
    int tx = threadIdx.x, ty = threadIdx.y;
    for (int i = ty; i < 32; i += 8) t[i][tx] = in[(size_t)(k0 + i) * Nd + n0 + tx];
    __syncthreads();
    for (int i = ty; i < 32; i += 8)
        out[(size_t)(n0 + i) * Kd + k0 + tx] = __float2bfloat16_rn(t[tx][i]);
}

// ---------------- bf16 mma.sync GEMM: 3-stage cp.async, 1 sync/iter ------------
// acc = A[M,K](bf16) @ Wt[N,K](bf16)^T, fp32 accum; + bias, then:
// EPI 0: relu -> bf16. EPI 1: raw fp32 -> Cf AND bf16 -> Cb. EPI 2: sqdiff partials.
// Block 256 thr = 8 warps (2m x 4n); block tile 128 x BN, k-chunk KB.
template <int BN, int KB, int EPI>
__global__ void __launch_bounds__(256, 2)
mma_gemm(const __nv_bfloat16* __restrict__ A, const __nv_bfloat16* __restrict__ Bt,
         const float* __restrict__ bias, __nv_bfloat16* __restrict__ Cb,
         float* __restrict__ Cf, const float* __restrict__ X,
         float* __restrict__ part, int N, int K) {
    extern __shared__ char smem[];
    __nv_bfloat16* smh = reinterpret_cast<__nv_bfloat16*>(smem);
    constexpr int LDT = KB + 8;               // halves; +16B/row pad -> conflict-free
    constexpr int A_TILE_H = 128 * LDT;
    constexpr int B_TILE_H = BN * LDT;
    constexpr int STAGE_H = A_TILE_H + B_TILE_H;
    constexpr int NTL = BN / 32;
    constexpr int WN = BN / 4;
    constexpr int CPR = KB / 8;               // 16B chunks per row
    constexpr int A_IT = (128 * CPR) / 256;
    constexpr int B_IT = (BN * CPR + 255) / 256;

    const int tid = threadIdx.x;
    const int wid = tid >> 5;
    const int lane = tid & 31;
    const int g = lane >> 2;
    const int t = lane & 3;
    const int warp_m = wid >> 2;
    const int warp_n = wid & 3;
    const int bm = blockIdx.y * 128, bn = blockIdx.x * BN;
    const uint32_t sb = smem_u32(smh);

    float acc[4][NTL][4];
#pragma unroll
    for (int mt = 0; mt < 4; mt++)
#pragma unroll
        for (int nt = 0; nt < NTL; nt++)
#pragma unroll
            for (int i = 0; i < 4; i++) acc[mt][nt][i] = 0.0f;

    const int NC = K / KB;

    auto prefetch = [&](int c, int s) {
        const int k0 = c * KB;
        const uint32_t base = sb + (uint32_t)s * STAGE_H * 2;
#pragma unroll
        for (int i = 0; i < A_IT; i++) {
            int idx = tid + i * 256;
            int r = idx / CPR, ch = idx % CPR;
            cp_async16(base + (r * LDT + ch * 8) * 2,
                       &A[(size_t)(bm + r) * K + k0 + ch * 8]);
        }
#pragma unroll
        for (int i = 0; i < B_IT; i++) {
            int idx = tid + i * 256;
            if ((BN * CPR) % 256 == 0 || idx < BN * CPR) {
                int r = idx / CPR, ch = idx % CPR;
                cp_async16(base + (A_TILE_H + r * LDT + ch * 8) * 2,
                           &Bt[(size_t)(bn + r) * K + k0 + ch * 8]);
            }
        }
    };

    auto compute = [&](int s) {
        const __nv_bfloat16* As = smh + s * STAGE_H;
        const __nv_bfloat16* Bs = As + A_TILE_H;
#pragma unroll
        for (int s16 = 0; s16 < KB / 16; s16++) {
            const int kb = s16 * 16 + 2 * t;
            uint32_t bf[NTL][2];
#pragma unroll
            for (int nt = 0; nt < NTL; nt++) {
                int nb = warp_n * WN + nt * 8 + g;
                bf[nt][0] = *reinterpret_cast<const uint32_t*>(&Bs[nb * LDT + kb]);
                bf[nt][1] = *reinterpret_cast<const uint32_t*>(&Bs[nb * LDT + kb + 8]);
            }
#pragma unroll
            for (int mt = 0; mt < 4; mt++) {
                int mb = warp_m * 64 + mt * 16 + g;
                uint32_t af[4];
                af[0] = *reinterpret_cast<const uint32_t*>(&As[mb * LDT + kb]);
                af[1] = *reinterpret_cast<const uint32_t*>(&As[(mb + 8) * LDT + kb]);
                af[2] = *reinterpret_cast<const uint32_t*>(&As[mb * LDT + kb + 8]);
                af[3] = *reinterpret_cast<const uint32_t*>(&As[(mb + 8) * LDT + kb + 8]);
#pragma unroll
                for (int nt = 0; nt < NTL; nt++) MMA_BF16(acc[mt][nt], af, bf[nt]);
            }
        }
    };

    // ---- 3-stage pipelined mainloop, single sync per iteration ----
    prefetch(0, 0);
    CP_COMMIT();
    if (NC > 1) { prefetch(1, 1); CP_COMMIT(); }
#pragma unroll 1
    for (int c = 0; c < NC; c++) {
        if (c + 1 < NC) CP_WAIT1(); else CP_WAIT0();
        __syncthreads();          // group c landed; all warps done reading stage (c+2)%3
        if (c + 2 < NC) { prefetch(c + 2, (c + 2) % 3); CP_COMMIT(); }
        compute(c % 3);
    }

    // ---- epilogue straight from accumulators ----
    float lsum = 0.0f;
#pragma unroll
    for (int mt = 0; mt < 4; mt++) {
#pragma unroll
        for (int nt = 0; nt < NTL; nt++) {
            int row = bm + warp_m * 64 + mt * 16 + g;
            int col = bn + warp_n * WN + nt * 8 + 2 * t;
            float b0 = bias[col], b1 = bias[col + 1];
            float v0 = acc[mt][nt][0] + b0, v1 = acc[mt][nt][1] + b1;
            float v2 = acc[mt][nt][2] + b0, v3 = acc[mt][nt][3] + b1;
            size_t i0 = (size_t)row * N + col;
            size_t i1 = (size_t)(row + 8) * N + col;
            if (EPI == 0) {
                v0 = fmaxf(v0, 0.0f); v1 = fmaxf(v1, 0.0f);
                v2 = fmaxf(v2, 0.0f); v3 = fmaxf(v3, 0.0f);
                *reinterpret_cast<__nv_bfloat162*>(&Cb[i0]) = __floats2bfloat162_rn(v0, v1);
                *reinterpret_cast<__nv_bfloat162*>(&Cb[i1]) = __floats2bfloat162_rn(v2, v3);
            } else if (EPI == 1) {
                *reinterpret_cast<float2*>(&Cf[i0]) = make_float2(v0, v1);
                *reinterpret_cast<float2*>(&Cf[i1]) = make_float2(v2, v3);
                *reinterpret_cast<__nv_bfloat162*>(&Cb[i0]) = __floats2bfloat162_rn(v0, v1);
                *reinterpret_cast<__nv_bfloat162*>(&Cb[i1]) = __floats2bfloat162_rn(v2, v3);
            } else {
                float2 x0 = *reinterpret_cast<const float2*>(&X[i0]);
                float2 x1 = *reinterpret_cast<const float2*>(&X[i1]);
                float d0 = v0 - x0.x, d1 = v1 - x0.y, d2 = v2 - x1.x, d3 = v3 - x1.y;
                lsum += d0 * d0 + d1 * d1 + d2 * d2 + d3 * d3;
            }
        }
    }
    if (EPI == 2) {
        __syncthreads();
        float* red = reinterpret_cast<float*>(smem);
        red[tid] = lsum;
        __syncthreads();
        for (int s2 = 128; s2 > 0; s2 >>= 1) {
            if (tid < s2) red[tid] += red[tid + s2];
            __syncthreads();
        }
        if (tid == 0) part[blockIdx.y * gridDim.x + blockIdx.x] = red[0];
    }
}

// ---------------- clustering pass A -------------------------------------------
__global__ void cluster_pass(const float* __restrict__ t1,
                             const float* __restrict__ clu,
                             float* __restrict__ out_predict) {
    __shared__ float cs[KCLU * NZ];
    __shared__ float u_s[KCLU];
    __shared__ float red[256];
    int tid = threadIdx.x;
    for (int i = tid; i < KCLU * NZ; i += 256) cs[i] = clu[i];
    if (tid < KCLU) u_s[tid] = 0.0f;
    __syncthreads();

    int p = blockIdx.x * 256 + tid;
    float zr[NZ];
    const float* zp = g_z + (size_t)p * NZ;
#pragma unroll
    for (int i = 0; i < NZ; i++) zr[i] = zp[i];

    float cm = (t1[p * 3 + 0] * 0.01f) * (t1[p * 3 + 1] * 0.01f) * (t1[p * 3 + 2] * 0.01f)
               * 0.99f + 1.0f;
    float s = 0.0f;
#pragma unroll
    for (int i = 0; i < NZ; i++) { zr[i] *= cm; s += zr[i]; }
    float mean = s * (1.0f / NZ);
    float var = 0.0f;
#pragma unroll
    for (int i = 0; i < NZ; i++) { float d = zr[i] - mean; var += d * d; }
    float isd = 1.0f / sqrtf(var * (1.0f / (NZ - 1)));
#pragma unroll
    for (int i = 0; i < NZ; i++) zr[i] = (zr[i] - mean) * isd;

    float sumq = 0.0f, best = -1.0f, best2 = -1.0f;
    int bi = 0;
    for (int j = 0; j < KCLU; j++) {
        const float* c = &cs[j * NZ];
        float d = 0.0f;
#pragma unroll
        for (int i = 0; i < NZ; i++) { float tt = zr[i] - c[i]; d += tt * tt; }
        float qu = EPSF + d;
        sumq += qu;
        if (qu > best) { best2 = best; best = qu; bi = j; }
        else if (qu > best2) best2 = qu;
    }
    out_predict[p] = (float)bi;
    atomicAdd(&g_cnt[bi], 1);
    if (best - best2 < GAP_TAU * best) {       // near-tie: flag for fp32 rescue
        int ii = atomicAdd(&g_nflag, 1);
        g_flaglist[ii] = p;
    }

    float inv = 1.0f / sumq;
    float Sl = 0.0f;
    float* qrow = g_q + (size_t)p * KCLU;
    for (int j = 0; j < KCLU; j++) {
        const float* c = &cs[j * NZ];
        float d = 0.0f;
#pragma unroll
        for (int i = 0; i < NZ; i++) { float tt = zr[i] - c[i]; d += tt * tt; }
        float qn = (EPSF + d) * inv;
        qrow[j] = qn;
        atomicAdd(&u_s[j], qn);
        float lq = logf(qn);
        float tq = (1.0f - qn) * (1.0f - qn) * lq * INDEXF;
        Sl += sqrtf(-1.0f / tq);
    }

    red[tid] = Sl;
    __syncthreads();
    for (int s2 = 128; s2 > 0; s2 >>= 1) {
        if (tid < s2) red[tid] += red[tid + s2];
        __syncthreads();
    }
    if (tid == 0) g_Spart[blockIdx.x] = red[0];
    __syncthreads();
    if (tid < KCLU) g_upart[blockIdx.x * KCLU + tid] = u_s[tid];
}

// ---------------- fp32 rescue for near-tie points ------------------------------
#define RB 8
__global__ void __launch_bounds__(256, 1)
rescue_kernel(const float* __restrict__ x, const float* __restrict__ t1,
              const float* __restrict__ clu,
              const float* __restrict__ We1, const float* __restrict__ be1,
              const float* __restrict__ We2, const float* __restrict__ be2,
              const float* __restrict__ We3, const float* __restrict__ be3,
              const float* __restrict__ Wz,  const float* __restrict__ bz,
              float* __restrict__ out_predict) {
    extern __shared__ float sm[];
    float* xb  = sm;                  // [1024][RB]
    float* hh  = xb + RB * 1024;      // [2048][RB]
    float* s1b = hh + RB * 2048;      // [512][RB]
    float* s2b = s1b + RB * 512;      // [512][RB]
    float* zz  = s2b + RB * 512;      // [RB][32]
    float* pz  = zz + RB * 32;        // [8][32][RB]
    float* dst = pz + 8 * 32 * RB;    // [128]
    const int tid = threadIdx.x;
    const int nf = g_nflag;

    for (int base = blockIdx.x * RB; base < nf; base += gridDim.x * RB) {
        const int cb = min(RB, nf - base);
        int plist[RB];
#pragma unroll
        for (int i = 0; i < RB; i++) plist[i] = g_flaglist[base + (i < cb ? i : 0)];
        __syncthreads();
        for (int k = tid; k < 1024; k += 256) {
#pragma unroll
            for (int i = 0; i < RB; i++)
                xb[k * RB + i] = x[(size_t)plist[i] * 1024 + k];
        }
        __syncthreads();
        for (int n = tid; n < 512; n += 256) {
            float acc[RB] = {};
            for (int k = 0; k < 1024; k++) {
                float w = We1[(size_t)k * 512 + n];
                float4 v0 = *reinterpret_cast<const float4*>(&xb[k * RB]);
                float4 v1 = *reinterpret_cast<const float4*>(&xb[k * RB + 4]);
                acc[0] += v0.x * w; acc[1] += v0.y * w; acc[2] += v0.z * w; acc[3] += v0.w * w;
                acc[4] += v1.x * w; acc[5] += v1.y * w; acc[6] += v1.z * w; acc[7] += v1.w * w;
            }
            float b = be1[n];
#pragma unroll
            for (int i = 0; i < RB; i++) s1b[n * RB + i] = fmaxf(acc[i] + b, 0.0f);
        }
        __syncthreads();
        for (int n = tid; n < 512; n += 256) {
            float acc[RB] = {};
            for (int k = 0; k < 512; k++) {
                float w = We2[(size_t)k * 512 + n];
                float4 v0 = *reinterpret_cast<const float4*>(&s1b[k * RB]);
                float4 v1 = *reinterpret_cast<const float4*>(&s1b[k * RB + 4]);
                acc[0] += v0.x * w; acc[1] += v0.y * w; acc[2] += v0.z * w; acc[3] += v0.w * w;
                acc[4] += v1.x * w; acc[5] += v1.y * w; acc[6] += v1.z * w; acc[7] += v1.w * w;
            }
            float b = be2[n];
#pragma unroll
            for (int i = 0; i < RB; i++) s2b[n * RB + i] = fmaxf(acc[i] + b, 0.0f);
        }
        __syncthreads();
        for (int n = tid; n < 2048; n += 256) {
            float acc[RB] = {};
            for (int k = 0; k < 512; k++) {
                float w = We3[(size_t)k * 2048 + n];
                float4 v0 = *reinterpret_cast<const float4*>(&s2b[k * RB]);
                float4 v1 = *reinterpret_cast<const float4*>(&s2b[k * RB + 4]);
                acc[0] += v0.x * w; acc[1] += v0.y * w; acc[2] += v0.z * w; acc[3] += v0.w * w;
                acc[4] += v1.x * w; acc[5] += v1.y * w; acc[6] += v1.z * w; acc[7] += v1.w * w;
            }
            float b = be3[n];
#pragma unroll
            for (int i = 0; i < RB; i++) hh[n * RB + i] = fmaxf(acc[i] + b, 0.0f);
        }
        __syncthreads();
        {
            int n = tid & 31, kc = tid >> 5;
            float acc[RB] = {};
            for (int k = kc * 256; k < kc * 256 + 256; k++) {
                float w = Wz[(size_t)k * 32 + n];
                float4 v0 = *reinterpret_cast<const float4*>(&hh[k * RB]);
                float4 v1 = *reinterpret_cast<const float4*>(&hh[k * RB + 4]);
                acc[0] += v0.x * w; acc[1] += v0.y * w; acc[2] += v0.z * w; acc[3] += v0.w * w;
                acc[4] += v1.x * w; acc[5] += v1.y * w; acc[6] += v1.z * w; acc[7] += v1.w * w;
            }
#pragma unroll
            for (int i = 0; i < RB; i++) pz[(kc * 32 + n) * RB + i] = acc[i];
        }
        __syncthreads();
        if (tid < 32) {
            int n = tid;
            float b = bz[n];
#pragma unroll
            for (int i = 0; i < RB; i++) {
                float s = 0.0f;
                for (int kc = 0; kc < 8; kc++) s += pz[(kc * 32 + n) * RB + i];
                zz[i * 32 + n] = s + b;
            }
        }
        __syncthreads();
        if (tid < cb) {
            int i = tid;
            int p = plist[i];
            float cm = (t1[p * 3 + 0] * 0.01f) * (t1[p * 3 + 1] * 0.01f) *
                       (t1[p * 3 + 2] * 0.01f) * 0.99f + 1.0f;
            float s = 0.0f;
            for (int k = 0; k < NZ; k++) { zz[i * 32 + k] *= cm; s += zz[i * 32 + k]; }
            float mean = s * (1.0f / NZ);
            float var = 0.0f;
            for (int k = 0; k < NZ; k++) { float d = zz[i * 32 + k] - mean; var += d * d; }
            float isd = 1.0f / sqrtf(var * (1.0f / (NZ - 1)));
            for (int k = 0; k < NZ; k++) zz[i * 32 + k] = (zz[i * 32 + k] - mean) * isd;
        }
        __syncthreads();
        for (int i = 0; i < cb; i++) {
            if (tid < KCLU) {
                float d = 0.0f;
                for (int k = 0; k < NZ; k++) {
                    float tt = zz[i * 32 + k] - clu[tid * NZ + k];
                    d += tt * tt;
                }
                dst[tid] = d;
            }
            __syncthreads();
            if (tid == 0) {
                float best = -1.0f; int bi = 0;
                for (int j = 0; j < KCLU; j++)
                    if (dst[j] > best) { best = dst[j]; bi = j; }
                int p = plist[i];
                int old = (int)out_predict[p];
                if (old != bi) {
                    atomicAdd(&g_cnt[old], -1);
                    atomicAdd(&g_cnt[bi], 1);
                    out_predict[p] = (float)bi;
                }
            }
            __syncthreads();
        }
    }
}

// ---------------- stats pass B -------------------------------------------------
__global__ void stats_kernel() {
    __shared__ float u[KCLU];
    __shared__ float sred[128];
    int tid = threadIdx.x;
    if (tid < KCLU) {
        float s = 0.0f;
        for (int b = 0; b < NBLK_PTS; b++) s += g_upart[b * KCLU + tid];
        u[tid] = s;
    }
    float sp = (tid < NBLK_PTS) ? g_Spart[tid] : 0.0f;
    sred[tid] = sp;
    __syncthreads();
    for (int s = 64; s > 0; s >>= 1) {
        if (tid < s) sred[tid] += sred[tid + s];
        __syncthreads();
    }
    if (tid == 0) {
        float S = sred[0];
        float um = 0.0f;
        for (int j = 0; j < KCLU; j++) um += u[j];
        um /= KCLU;
        float uv = 0.0f;
        for (int j = 0; j < KCLU; j++) { float d = u[j] - um; uv += d * d; }
        float usd = sqrtf(uv / (KCLU - 1));

        float v[KCLU];
        float vm = 0.0f;
        for (int j = 0; j < KCLU; j++) {
            int c = g_cnt[j]; if (c < 1) c = 1;
            v[j] = sqrtf((float)c) * S;
            vm += v[j];
        }
        vm /= KCLU;
        float vv = 0.0f;
        for (int j = 0; j < KCLU; j++) { float d = v[j] - vm; vv += d * d; }
        float vsd = sqrtf(vv / (KCLU - 1));

        float umin = 1e30f, vmin = 1e30f;
        for (int j = 0; j < KCLU; j++) {
            float un = (u[j] - um) / usd;
            float vn = (v[j] - vm) / vsd;
            u[j] = un; v[j] = vn;
            if (un < umin) umin = un;
            if (vn < vmin) vmin = vn;
        }
        for (int j = 0; j < KCLU; j++)
            g_f[j] = (u[j] - umin + 0.001f) + (v[j] - vmin + 0.001f) + 1.0f;
    }
}

// ---------------- KL pass C -----------------------------------------------------
__global__ void kl_pass() {
    __shared__ float fs[KCLU];
    __shared__ float red[256];
    int tid = threadIdx.x;
    if (tid < KCLU) fs[tid] = g_f[tid];
    __syncthreads();
    int p = blockIdx.x * 256 + tid;
    const float* qrow = g_q + (size_t)p * KCLU;
    float sw = 0.0f;
    for (int j = 0; j < KCLU; j++) { float q = qrow[j]; sw += q * q / fs[j]; }
    float inv = 1.0f / sw;
    float kl = 0.0f;
    for (int j = 0; j < KCLU; j++) {
        float q = qrow[j];
        float pj = q * q / fs[j] * inv;
        kl += pj * (logf(pj) - logf(q));
    }
    red[tid] = kl;
    __syncthreads();
    for (int s2 = 128; s2 > 0; s2 >>= 1) {
        if (tid < s2) red[tid] += red[tid + s2];
        __syncthreads();
    }
    if (tid == 0) g_klpart[blockIdx.x] = red[0];
}

// ---------------- final loss ----------------------------------------------------
__global__ void final_kernel(const float* __restrict__ clu, float* __restrict__ out) {
    __shared__ float red[256];
    int tid = threadIdx.x;
    float kl = 0.0f;
    for (int i = tid; i < NBLK_PTS; i += 256) kl += g_klpart[i];
    float re = 0.0f;
    for (int i = tid; i < NBLK_RE; i += 256) re += g_repart[i];
    float D = 0.0f;
    for (int idx = tid; idx < KCLU * KCLU; idx += 256) {
        int i = idx / KCLU, j = idx % KCLU;
        float d = 0.0f;
        for (int kk = 0; kk < NZ; kk++) {
            float t = clu[i * NZ + kk] - clu[j * NZ + kk];
            d += t * t;
        }
        D += d;
    }
    red[tid] = kl; __syncthreads();
    for (int s = 128; s > 0; s >>= 1) { if (tid < s) red[tid] += red[tid + s]; __syncthreads(); }
    float kls = red[0]; __syncthreads();
    red[tid] = re; __syncthreads();
    for (int s = 128; s > 0; s >>= 1) { if (tid < s) red[tid] += red[tid + s]; __syncthreads(); }
    float res = red[0]; __syncthreads();
    red[tid] = D; __syncthreads();
    for (int s = 128; s > 0; s >>= 1) { if (tid < s) red[tid] += red[tid + s]; __syncthreads(); }
    if (tid == 0) {
        float kl_loss = 0.01f * kls / ((float)N_PTS * (float)KCLU);
        float re_loss = res / ((float)N_PTS * 1024.0f);
        float mean_d = red[0] / (float)(KCLU * KCLU - KCLU);
        out[N_PTS] = kl_loss + re_loss + 0.01f / mean_d;
    }
}

// ---------------- host ----------------------------------------------------------
extern "C" void kernel_launch(void* const* d_in, const int* in_sizes, int n_in,
                              void* d_out, int out_size) {
    const float* x   = (const float*)d_in[0];
    const float* t1  = (const float*)d_in[1];
    const float* clu = (const float*)d_in[2];
    const float* We1 = (const float*)d_in[3];  const float* be1 = (const float*)d_in[4];
    const float* We2 = (const float*)d_in[5];  const float* be2 = (const float*)d_in[6];
    const float* We3 = (const float*)d_in[7];  const float* be3 = (const float*)d_in[8];
    const float* Wz  = (const float*)d_in[9];  const float* bz  = (const float*)d_in[10];
    const float* Wd1 = (const float*)d_in[11]; const float* bd1 = (const float*)d_in[12];
    const float* Wd2 = (const float*)d_in[13]; const float* bd2 = (const float*)d_in[14];
    const float* Wd3 = (const float*)d_in[15]; const float* bd3 = (const float*)d_in[16];
    const float* Wxb = (const float*)d_in[17]; const float* bxb = (const float*)d_in[18];
    float* out = (float*)d_out;

    __nv_bfloat16 *xb, *Pb, *h1b, *h2b, *zbh, *wbt;
    float *zf, *repart;
    cudaGetSymbolAddress((void**)&xb,  g_xb);
    cudaGetSymbolAddress((void**)&Pb,  g_Pb);
    cudaGetSymbolAddress((void**)&h1b, g_h1b);
    cudaGetSymbolAddress((void**)&h2b, g_h2b);
    cudaGetSymbolAddress((void**)&zbh, g_zbh);
    cudaGetSymbolAddress((void**)&wbt, g_wbt);
    cudaGetSymbolAddress((void**)&zf,  g_z);
    cudaGetSymbolAddress((void**)&repart, g_repart);

    constexpr int SM_128 = (128 * 72 + 128 * 72) * 2 * 3;   // 110592 B (KB=64)
    constexpr int SM_32  = (128 * 72 + 32 * 72) * 2 * 3;    //  69120 B (BN=32,KB=64)
    constexpr int SM_D1  = (128 * 40 + 128 * 40) * 2 * 3;   //  61440 B (KB=32)
    constexpr int SM_RES = (RB * 1024 + RB * 2048 + RB * 512 + RB * 512 + RB * 32
                            + 8 * 32 * RB + 128) * 4;
    cudaFuncSetAttribute(mma_gemm<128, 64, 0>, cudaFuncAttributeMaxDynamicSharedMemorySize, SM_128);
    cudaFuncSetAttribute(mma_gemm<32, 64, 1>,  cudaFuncAttributeMaxDynamicSharedMemorySize, SM_32);
    cudaFuncSetAttribute(mma_gemm<128, 32, 0>, cudaFuncAttributeMaxDynamicSharedMemorySize, SM_D1);
    cudaFuncSetAttribute(mma_gemm<128, 64, 2>, cudaFuncAttributeMaxDynamicSharedMemorySize, SM_128);
    cudaFuncSetAttribute(rescue_kernel, cudaFuncAttributeMaxDynamicSharedMemorySize, SM_RES);

    init_kernel<<<1, 128>>>();

    // prep: x -> bf16; weights -> transposed bf16 [N,K]
    {
        int n2 = N_PTS * 1024 / 2;
        conv_bf16_kernel<<<(n2 + 255) / 256, 256>>>((const float2*)x, (__nv_bfloat162*)xb, n2);
    }
    dim3 tb(32, 8);
    tconv_kernel<<<dim3(512 / 32, 1024 / 32), tb>>>(We1, wbt + OFF_WE1, 1024, 512);
    tconv_kernel<<<dim3(512 / 32, 512 / 32), tb>>>(We2, wbt + OFF_WE2, 512, 512);
    tconv_kernel<<<dim3(2048 / 32, 512 / 32), tb>>>(We3, wbt + OFF_WE3, 512, 2048);
    tconv_kernel<<<dim3(1, 2048 / 32), tb>>>(Wz, wbt + OFF_WZ, 2048, 32);
    tconv_kernel<<<dim3(2048 / 32, 1), tb>>>(Wd1, wbt + OFF_WD1, 32, 2048);
    tconv_kernel<<<dim3(512 / 32, 2048 / 32), tb>>>(Wd2, wbt + OFF_WD2, 2048, 512);
    tconv_kernel<<<dim3(512 / 32, 512 / 32), tb>>>(Wd3, wbt + OFF_WD3, 512, 512);
    tconv_kernel<<<dim3(1024 / 32, 512 / 32), tb>>>(Wxb, wbt + OFF_WXB, 512, 1024);

    const dim3 blk(256);
    const int MB = N_PTS / 128;  // 232

    // encoder
    mma_gemm<128, 64, 0><<<dim3(4, MB), blk, SM_128>>>(xb, wbt + OFF_WE1, be1, h1b, nullptr, nullptr, nullptr, 512, 1024);
    mma_gemm<128, 64, 0><<<dim3(4, MB), blk, SM_128>>>(h1b, wbt + OFF_WE2, be2, h2b, nullptr, nullptr, nullptr, 512, 512);
    mma_gemm<128, 64, 0><<<dim3(16, MB), blk, SM_128>>>(h2b, wbt + OFF_WE3, be3, Pb, nullptr, nullptr, nullptr, 2048, 512);
    mma_gemm<32, 64, 1><<<dim3(1, MB), blk, SM_32>>>(Pb, wbt + OFF_WZ, bz, zbh, zf, nullptr, nullptr, 32, 2048);
    // decoder
    mma_gemm<128, 32, 0><<<dim3(16, MB), blk, SM_D1>>>(zbh, wbt + OFF_WD1, bd1, Pb, nullptr, nullptr, nullptr, 2048, 32);
    mma_gemm<128, 64, 0><<<dim3(4, MB), blk, SM_128>>>(Pb, wbt + OFF_WD2, bd2, h1b, nullptr, nullptr, nullptr, 512, 2048);
    mma_gemm<128, 64, 0><<<dim3(4, MB), blk, SM_128>>>(h1b, wbt + OFF_WD3, bd3, h2b, nullptr, nullptr, nullptr, 512, 512);
    mma_gemm<128, 64, 2><<<dim3(8, MB), blk, SM_128>>>(h2b, wbt + OFF_WXB, bxb, nullptr, nullptr, x, repart, 1024, 512);

    // clustering + rescue + loss
    cluster_pass<<<NBLK_PTS, 256>>>(t1, clu, out);
    rescue_kernel<<<148, 256, SM_RES>>>(x, t1, clu, We1, be1, We2, be2, We3, be3, Wz, bz, out);
    stats_kernel<<<1, 128>>>();
    kl_pass<<<NBLK_PTS, 256>>>();
    final_kernel<<<1, 256>>>(clu, out);

    int extra = out_size - (N_PTS + 1);
    if (extra > 0) fill_zero_kernel<<<(extra + 255) / 256, 256>>>(out + N_PTS + 1, extra);
}